// round 9
// baseline (speedup 1.0000x reference)
#include <cuda_runtime.h>
#include <cuda_bf16.h>
#include <stdint.h>

#define BB 32
#define SS 8192
#define DD 512
#define MM 16
#define CHUNKS 32
#define CSZ (SS/CHUNKS)      /* 256 */
#define TS 32
#define NT (CSZ/TS)          /* 8 */
#define NTHREADS 512
#define NW 16                /* warps */

/* smem byte offsets */
#define OXH 0u               /* xh[2][32][512] bf16 swizzled, buf stride 32768 */
#define OXL 65536u           /* xl likewise */
#define OSH (OXH + 32768u)   /* seeds hi [16][520] bf16 (prologue only, xh buf1) */
#define OSL (OXL + 32768u)
#define ORED 131072u         /* fp32 [16][32][17] = 34816 B */
#define OPTH 165888u         /* P^T hi [16][40] bf16, row stride 80 B */
#define OPTL 167168u
#define OLRED 168448u        /* float[512] */
#define OLINV 170496u        /* float[16] */
#define OFLAG 170560u
#define SMEMSZ 170624u

__device__ float g_partA[BB*CHUNKS*MM*DD];
__device__ float g_partL[BB*CHUNKS*MM];
__device__ unsigned g_cnt[BB];

__device__ __forceinline__ unsigned sptr(const void* p) {
    return (unsigned)__cvta_generic_to_shared(p);
}
__device__ __forceinline__ void ldm_x4(unsigned* r, unsigned a) {
    asm volatile("ldmatrix.sync.aligned.m8n8.x4.shared.b16 {%0,%1,%2,%3}, [%4];"
                 : "=r"(r[0]), "=r"(r[1]), "=r"(r[2]), "=r"(r[3]) : "r"(a));
}
__device__ __forceinline__ void ldm_x2(unsigned* r, unsigned a) {
    asm volatile("ldmatrix.sync.aligned.m8n8.x2.shared.b16 {%0,%1}, [%2];"
                 : "=r"(r[0]), "=r"(r[1]) : "r"(a));
}
__device__ __forceinline__ void ldm_x4t(unsigned* r, unsigned a) {
    asm volatile("ldmatrix.sync.aligned.m8n8.x4.trans.shared.b16 {%0,%1,%2,%3}, [%4];"
                 : "=r"(r[0]), "=r"(r[1]), "=r"(r[2]), "=r"(r[3]) : "r"(a));
}
__device__ __forceinline__ void mma(float* c, const unsigned* a, const unsigned* b) {
    asm volatile("mma.sync.aligned.m16n8k16.row.col.f32.bf16.bf16.f32 "
                 "{%0,%1,%2,%3}, {%4,%5,%6,%7}, {%8,%9}, {%0,%1,%2,%3};"
                 : "+f"(c[0]), "+f"(c[1]), "+f"(c[2]), "+f"(c[3])
                 : "r"(a[0]), "r"(a[1]), "r"(a[2]), "r"(a[3]), "r"(b[0]), "r"(b[1]));
}
__device__ __forceinline__ void splitf4(float4 v, uint2& h, uint2& l) {
    __nv_bfloat162 h01 = __float22bfloat162_rn(make_float2(v.x, v.y));
    __nv_bfloat162 h23 = __float22bfloat162_rn(make_float2(v.z, v.w));
    float2 r01 = make_float2(v.x - __bfloat162float(h01.x), v.y - __bfloat162float(h01.y));
    float2 r23 = make_float2(v.z - __bfloat162float(h23.x), v.w - __bfloat162float(h23.y));
    __nv_bfloat162 l01 = __float22bfloat162_rn(r01);
    __nv_bfloat162 l23 = __float22bfloat162_rn(r23);
    h.x = *(unsigned*)&h01; h.y = *(unsigned*)&h23;
    l.x = *(unsigned*)&l01; l.y = *(unsigned*)&l23;
}

__global__ void __launch_bounds__(NTHREADS, 1)
attn_pool_mma(const float* __restrict__ x, const float* __restrict__ seeds,
              float* __restrict__ out) {
    extern __shared__ char smc[];
    const unsigned sb = sptr(smc);
    float* redp = (float*)(smc + ORED);
    float* lred = (float*)(smc + OLRED);
    float* linv = (float*)(smc + OLINV);
    unsigned* flag = (unsigned*)(smc + OFLAG);

    const int t = threadIdx.x, w = t >> 5, l = t & 31;
    const int chunk = blockIdx.x, b = blockIdx.y;
    const int lrow = (l & 7) + ((l >> 3) & 1) * 8;  /* ldm x4 A-tile row */
    const int lsel = l >> 4;                        /* x4: k-granule select */
    const int qr = l >> 2, qc = (l & 3) * 2;        /* c-frag (row, col) base */

    const float4* xb4 = (const float4*)(x + ((size_t)b * SS + (size_t)chunk * CSZ) * DD);

    /* ---- prologue: stage seeds + tile0 ---- */
    float4 sg[4], g[8];
#pragma unroll
    for (int i = 0; i < 4; i++) sg[i] = ((const float4*)seeds)[t + i * NTHREADS];
#pragma unroll
    for (int i = 0; i < 8; i++) g[i] = xb4[t + i * NTHREADS];

#pragma unroll
    for (int i = 0; i < 4; i++) {
        int idx = t + i * NTHREADS, r = idx >> 7, c4 = idx & 127;
        uint2 h, lo;
        splitf4(sg[i], h, lo);
        *(uint2*)(smc + OSH + r * 1040 + c4 * 8) = h;
        *(uint2*)(smc + OSL + r * 1040 + c4 * 8) = lo;
    }
    __syncthreads();

    /* seed B-fragments (register-resident): warp k-slice [32w, 32w+32) */
    unsigned sbh[2][2][2], sbl[2][2][2];
#pragma unroll
    for (int ks = 0; ks < 2; ks++)
#pragma unroll
        for (int nb = 0; nb < 2; nb++) {
            int row = nb * 8 + (l & 7);
            int boff = (w * 32 + ks * 16) * 2 + ((l >> 3) & 1) * 16;
            ldm_x2(sbh[ks][nb], sb + OSH + row * 1040 + boff);
            ldm_x2(sbl[ks][nb], sb + OSL + row * 1040 + boff);
        }
    __syncthreads();

    /* tile0 -> bf16 buf0 (16B-granule XOR swizzle) */
#pragma unroll
    for (int i = 0; i < 8; i++) {
        int idx = t + i * NTHREADS, r = idx >> 7, c4 = idx & 127;
        uint2 h, lo;
        splitf4(g[i], h, lo);
        unsigned off = r * 1024 + ((((unsigned)c4 >> 1) ^ (r & 7)) << 4) + (c4 & 1) * 8;
        *(uint2*)(smc + OXH + off) = h;
        *(uint2*)(smc + OXL + off) = lo;
    }
    __syncthreads();

    float acc[4][4];
#pragma unroll
    for (int i = 0; i < 4; i++)
#pragma unroll
        for (int j = 0; j < 4; j++) acc[i][j] = 0.f;
    float lsum = 0.f;

    for (int tile = 0; tile < NT; ++tile) {
        const unsigned cur = (tile & 1) * 32768u, nxt = ((tile + 1) & 1) * 32768u;
        if (tile + 1 < NT) {
#pragma unroll
            for (int i = 0; i < 8; i++)
                g[i] = xb4[(size_t)(tile + 1) * TS * 128 + t + i * NTHREADS];
        }

        /* ---- phase 1: score partials, warp k-slice [32w, 32w+32) ---- */
        float c[2][2][4];
#pragma unroll
        for (int mb = 0; mb < 2; mb++)
#pragma unroll
            for (int nb = 0; nb < 2; nb++)
#pragma unroll
                for (int j = 0; j < 4; j++) c[mb][nb][j] = 0.f;
#pragma unroll
        for (int ks = 0; ks < 2; ks++)
#pragma unroll
            for (int mb = 0; mb < 2; mb++) {
                int s = mb * 16 + lrow;
                unsigned gr = (unsigned)((4 * w + 2 * ks + lsel) ^ (s & 7));
                unsigned ah[4], al[4];
                ldm_x4(ah, sb + OXH + cur + s * 1024 + (gr << 4));
                ldm_x4(al, sb + OXL + cur + s * 1024 + (gr << 4));
                mma(c[mb][0], ah, sbh[ks][0]);
                mma(c[mb][0], ah, sbl[ks][0]);
                mma(c[mb][0], al, sbh[ks][0]);
                mma(c[mb][1], ah, sbh[ks][1]);
                mma(c[mb][1], ah, sbl[ks][1]);
                mma(c[mb][1], al, sbh[ks][1]);
            }
#pragma unroll
        for (int mb = 0; mb < 2; mb++)
#pragma unroll
            for (int nb = 0; nb < 2; nb++) {
                int i0 = w * 544 + (mb * 16 + qr) * 17 + nb * 8 + qc;
                redp[i0] = c[mb][nb][0];
                redp[i0 + 1] = c[mb][nb][1];
                redp[i0 + 8 * 17] = c[mb][nb][2];
                redp[i0 + 8 * 17 + 1] = c[mb][nb][3];
            }
        __syncthreads();

        /* ---- reduce over 16 warps, exp, P^T hi/lo (thread <-> (s,m) 1:1) ---- */
        {
            int s0 = t >> 4, m0 = t & 15;
            float a0 = 0.f;
#pragma unroll
            for (int ww = 0; ww < NW; ww++)
                a0 += redp[ww * 544 + s0 * 17 + m0];
            float e0 = __expf(a0);   /* scores bounded: no max-subtraction needed */
            lsum += e0;
            __nv_bfloat16 h0 = __float2bfloat16(e0);
            __nv_bfloat16 o0 = __float2bfloat16(e0 - __bfloat162float(h0));
            *(__nv_bfloat16*)(smc + OPTH + m0 * 80 + s0 * 2) = h0;
            *(__nv_bfloat16*)(smc + OPTL + m0 * 80 + s0 * 2) = o0;
        }
        __syncthreads();

        /* ---- phase 2: acc[16m, 32d slice] += P^T @ X ---- */
        unsigned pah[2][4], pal[2][4];
#pragma unroll
        for (int ks = 0; ks < 2; ks++) {
            unsigned ad = lrow * 80 + ks * 32 + lsel * 16;
            ldm_x4(pah[ks], sb + OPTH + ad);
            ldm_x4(pal[ks], sb + OPTL + ad);
        }
#pragma unroll
        for (int nt = 0; nt < 4; nt++) {
            int gn = 4 * w + nt;
            int sx = (l >> 3) * 8 + (l & 7);             /* 0..31: 4 tiles of 8 rows */
            unsigned ga = sb + OXH + cur + sx * 1024 + ((unsigned)(gn ^ (sx & 7)) << 4);
            unsigned bh[4], bl[4];
            ldm_x4t(bh, ga);
            ldm_x4t(bl, ga + (OXL - OXH));
            mma(acc[nt], pah[0], bh);       /* ks0: bh[0],bh[1] */
            mma(acc[nt], pah[0], bl);
            mma(acc[nt], pal[0], bh);
            mma(acc[nt], pah[1], bh + 2);   /* ks1: bh[2],bh[3] */
            mma(acc[nt], pah[1], bl + 2);
            mma(acc[nt], pal[1], bh + 2);
        }

        /* ---- convert + store next tile ---- */
        if (tile + 1 < NT) {
#pragma unroll
            for (int i = 0; i < 8; i++) {
                int idx = t + i * NTHREADS, r = idx >> 7, c4 = idx & 127;
                uint2 h, lo;
                splitf4(g[i], h, lo);
                unsigned off = nxt + r * 1024 +
                               ((((unsigned)c4 >> 1) ^ (r & 7)) << 4) + (c4 & 1) * 8;
                *(uint2*)(smc + OXH + off) = h;
                *(uint2*)(smc + OXL + off) = lo;
            }
        }
        __syncthreads();
    }

    /* ---- per-chunk partials ---- */
    {
        size_t base = ((size_t)(b * CHUNKS + chunk) * MM) * DD;
#pragma unroll
        for (int nt = 0; nt < 4; nt++) {
            int d0 = w * 32 + nt * 8 + qc;
            *(float2*)&g_partA[base + (size_t)qr * DD + d0] =
                make_float2(acc[nt][0], acc[nt][1]);
            *(float2*)&g_partA[base + (size_t)(qr + 8) * DD + d0] =
                make_float2(acc[nt][2], acc[nt][3]);
        }
        lred[t] = lsum;
    }
    __syncthreads();
    if (t < MM) {
        float tot = 0.f;
#pragma unroll
        for (int i = 0; i < NTHREADS; i += MM) tot += lred[i + t];
        g_partL[(b * CHUNKS + chunk) * MM + t] = tot;
    }

    /* ---- last-CTA-per-batch fused merge ---- */
    __threadfence();
    __syncthreads();
    if (t == 0) {
        unsigned old = atomicAdd(&g_cnt[b], 1u);
        flag[0] = ((old & (CHUNKS - 1)) == (CHUNKS - 1)) ? 1u : 0u;
    }
    __syncthreads();
    if (flag[0]) {
        __threadfence();
        if (t < MM) {
            float sl = 0.f;
#pragma unroll
            for (int c2 = 0; c2 < CHUNKS; c2++)
                sl += g_partL[(b * CHUNKS + c2) * MM + t];
            linv[t] = 1.f / sl;
        }
        __syncthreads();
        float4* ob = (float4*)(out + (size_t)b * MM * DD);
#pragma unroll
        for (int i = 0; i < 4; i++) {
            int o = t + i * NTHREADS;
            int m = o >> 7, d4 = o & 127;
            float4 a = make_float4(0.f, 0.f, 0.f, 0.f);
#pragma unroll 8
            for (int c2 = 0; c2 < CHUNKS; c2++) {
                const float4* pa =
                    (const float4*)&g_partA[(((size_t)(b * CHUNKS + c2)) * MM + m) * DD];
                float4 v = pa[d4];
                a.x += v.x; a.y += v.y; a.z += v.z; a.w += v.w;
            }
            float inv = linv[m];
            ob[o] = make_float4(a.x * inv, a.y * inv, a.z * inv, a.w * inv);
        }
    }
}

extern "C" void kernel_launch(void* const* d_in, const int* in_sizes, int n_in,
                              void* d_out, int out_size) {
    const float* x = (const float*)d_in[0];
    const float* seeds = (const float*)d_in[1];
    float* out = (float*)d_out;

    cudaFuncSetAttribute(attn_pool_mma,
                         cudaFuncAttributeMaxDynamicSharedMemorySize, (int)SMEMSZ);
    dim3 grid(CHUNKS, BB);
    attn_pool_mma<<<grid, NTHREADS, SMEMSZ>>>(x, seeds, out);
}

// round 10
// speedup vs baseline: 1.2171x; 1.2171x over previous
#include <cuda_runtime.h>
#include <cuda_bf16.h>
#include <stdint.h>

#define BB 32
#define SS 8192
#define DD 512
#define MM 16
#define CHUNKS 32
#define CSZ (SS/CHUNKS)      /* 256 */
#define TS 32
#define NT (CSZ/TS)          /* 8 */
#define NTHREADS 256

/* smem byte offsets */
#define OXH 0u               /* xh[2][32][512] bf16 swizzled, buf stride 32768 */
#define OXL 65536u           /* xl likewise */
#define OSH (OXH + 32768u)   /* seeds hi [16][520] bf16 (prologue only, xh buf1) */
#define OSL (OXL + 32768u)
#define ORED 131072u         /* fp32 [8][32][17] = 17408 B */
#define OPTH 148480u         /* P^T hi [16][40] bf16, row stride 80 B */
#define OPTL 149760u
#define OLRED 151040u        /* float[256] */
#define OLINV 152064u        /* float[16] */
#define OFLAG 152128u
#define SMEMSZ 152192u

__device__ float g_partA[BB*CHUNKS*MM*DD];
__device__ float g_partL[BB*CHUNKS*MM];
__device__ unsigned g_cnt[BB];

__device__ __forceinline__ unsigned sptr(const void* p) {
    return (unsigned)__cvta_generic_to_shared(p);
}
__device__ __forceinline__ void ldm_x4(unsigned* r, unsigned a) {
    asm volatile("ldmatrix.sync.aligned.m8n8.x4.shared.b16 {%0,%1,%2,%3}, [%4];"
                 : "=r"(r[0]), "=r"(r[1]), "=r"(r[2]), "=r"(r[3]) : "r"(a));
}
__device__ __forceinline__ void ldm_x2(unsigned* r, unsigned a) {
    asm volatile("ldmatrix.sync.aligned.m8n8.x2.shared.b16 {%0,%1}, [%2];"
                 : "=r"(r[0]), "=r"(r[1]) : "r"(a));
}
__device__ __forceinline__ void ldm_x4t(unsigned* r, unsigned a) {
    asm volatile("ldmatrix.sync.aligned.m8n8.x4.trans.shared.b16 {%0,%1,%2,%3}, [%4];"
                 : "=r"(r[0]), "=r"(r[1]), "=r"(r[2]), "=r"(r[3]) : "r"(a));
}
__device__ __forceinline__ void mma(float* c, const unsigned* a, const unsigned* b) {
    asm volatile("mma.sync.aligned.m16n8k16.row.col.f32.bf16.bf16.f32 "
                 "{%0,%1,%2,%3}, {%4,%5,%6,%7}, {%8,%9}, {%0,%1,%2,%3};"
                 : "+f"(c[0]), "+f"(c[1]), "+f"(c[2]), "+f"(c[3])
                 : "r"(a[0]), "r"(a[1]), "r"(a[2]), "r"(a[3]), "r"(b[0]), "r"(b[1]));
}
__device__ __forceinline__ void splitf4(float4 v, uint2& h, uint2& l) {
    __nv_bfloat162 h01 = __float22bfloat162_rn(make_float2(v.x, v.y));
    __nv_bfloat162 h23 = __float22bfloat162_rn(make_float2(v.z, v.w));
    float2 r01 = make_float2(v.x - __bfloat162float(h01.x), v.y - __bfloat162float(h01.y));
    float2 r23 = make_float2(v.z - __bfloat162float(h23.x), v.w - __bfloat162float(h23.y));
    __nv_bfloat162 l01 = __float22bfloat162_rn(r01);
    __nv_bfloat162 l23 = __float22bfloat162_rn(r23);
    h.x = *(unsigned*)&h01; h.y = *(unsigned*)&h23;
    l.x = *(unsigned*)&l01; l.y = *(unsigned*)&l23;
}

__global__ void __launch_bounds__(NTHREADS, 1)
attn_pool_mma(const float* __restrict__ x, const float* __restrict__ seeds,
              float* __restrict__ out) {
    extern __shared__ char smc[];
    const unsigned sb = sptr(smc);
    float* redp = (float*)(smc + ORED);
    float* lred = (float*)(smc + OLRED);
    float* linv = (float*)(smc + OLINV);
    unsigned* flag = (unsigned*)(smc + OFLAG);

    const int t = threadIdx.x, w = t >> 5, l = t & 31;
    const int chunk = blockIdx.x, b = blockIdx.y;
    const int lrow = (l & 7) + ((l >> 3) & 1) * 8;  /* ldm x4 A-tile row */
    const int lsel = l >> 4;                        /* x4 k-granule select */
    const int qr = l >> 2, qc = (l & 3) * 2;        /* c-frag (row, col) base */

    const float4* xb4 = (const float4*)(x + ((size_t)b * SS + (size_t)chunk * CSZ) * DD);

    /* ---- prologue ---- */
    float4 sg[8], g[16];
#pragma unroll
    for (int i = 0; i < 8; i++) sg[i] = ((const float4*)seeds)[t + i * NTHREADS];
#pragma unroll
    for (int i = 0; i < 16; i++) g[i] = xb4[t + i * NTHREADS];   /* tile 0 */

#pragma unroll
    for (int i = 0; i < 8; i++) {
        int idx = t + i * NTHREADS, r = idx >> 7, c4 = idx & 127;
        uint2 h, lo;
        splitf4(sg[i], h, lo);
        *(uint2*)(smc + OSH + r * 1040 + c4 * 8) = h;
        *(uint2*)(smc + OSL + r * 1040 + c4 * 8) = lo;
    }
    __syncthreads();

    /* seed B-fragments, register-resident: warp k-slice [64w, 64w+64) */
    unsigned sbh[4][2][2], sbl[4][2][2];
#pragma unroll
    for (int ks = 0; ks < 4; ks++)
#pragma unroll
        for (int nb = 0; nb < 2; nb++) {
            int row = nb * 8 + (l & 7);
            int boff = (w * 64 + ks * 16) * 2 + ((l >> 3) & 1) * 16;
            ldm_x2(sbh[ks][nb], sb + OSH + row * 1040 + boff);
            ldm_x2(sbl[ks][nb], sb + OSL + row * 1040 + boff);
        }
    __syncthreads();

    /* convert tile 0 -> buf0 */
#pragma unroll
    for (int i = 0; i < 16; i++) {
        int idx = t + i * NTHREADS, r = idx >> 7, c4 = idx & 127;
        uint2 h, lo;
        splitf4(g[i], h, lo);
        unsigned off = r * 1024 + ((((unsigned)c4 >> 1) ^ (r & 7)) << 4) + (c4 & 1) * 8;
        *(uint2*)(smc + OXH + off) = h;
        *(uint2*)(smc + OXL + off) = lo;
    }
    /* stage tile 1 */
#pragma unroll
    for (int i = 0; i < 16; i++)
        g[i] = xb4[(size_t)TS * 128 + t + i * NTHREADS];

    float acc[8][4];
#pragma unroll
    for (int i = 0; i < 8; i++)
#pragma unroll
        for (int j = 0; j < 4; j++) acc[i][j] = 0.f;
    float lsum = 0.f;

    /* ---- skewed pipeline: block1 = phase1(tl) || phase2(tl-1); block2 = reduce/exp/convert ---- */
    for (int tl = 0; tl <= NT; ++tl) {
        __syncthreads();  /* buf[tl&1] converted; P^T(tl-1) ready; redp free */
        const unsigned c1 = (unsigned)(tl & 1) * 32768u;
        const unsigned c2 = (unsigned)((tl + 1) & 1) * 32768u;  /* parity of tl-1 */

        if (tl < NT) {
            /* phase1(tl): score partials, warp k-slice [64w,64w+64) */
            float c[2][2][4];
#pragma unroll
            for (int mb = 0; mb < 2; mb++)
#pragma unroll
                for (int nb = 0; nb < 2; nb++)
#pragma unroll
                    for (int j = 0; j < 4; j++) c[mb][nb][j] = 0.f;
#pragma unroll
            for (int ks = 0; ks < 4; ks++)
#pragma unroll
                for (int mb = 0; mb < 2; mb++) {
                    int s = mb * 16 + lrow;
                    unsigned gr = (unsigned)((8 * w + 2 * ks + lsel) ^ (s & 7));
                    unsigned ah[4], al[4];
                    ldm_x4(ah, sb + OXH + c1 + s * 1024 + (gr << 4));
                    ldm_x4(al, sb + OXL + c1 + s * 1024 + (gr << 4));
                    mma(c[mb][0], ah, sbh[ks][0]);
                    mma(c[mb][0], ah, sbl[ks][0]);
                    mma(c[mb][0], al, sbh[ks][0]);
                    mma(c[mb][1], ah, sbh[ks][1]);
                    mma(c[mb][1], ah, sbl[ks][1]);
                    mma(c[mb][1], al, sbh[ks][1]);
                }
#pragma unroll
            for (int mb = 0; mb < 2; mb++)
#pragma unroll
                for (int nb = 0; nb < 2; nb++) {
                    int i0 = w * 544 + (mb * 16 + qr) * 17 + nb * 8 + qc;
                    redp[i0] = c[mb][nb][0];
                    redp[i0 + 1] = c[mb][nb][1];
                    redp[i0 + 8 * 17] = c[mb][nb][2];
                    redp[i0 + 8 * 17 + 1] = c[mb][nb][3];
                }
        }

        if (tl > 0) {
            /* phase2(tl-1): acc[16m, 64d slice] += P^T @ X */
            unsigned pah[2][4], pal[2][4];
#pragma unroll
            for (int ks = 0; ks < 2; ks++) {
                unsigned ad = lrow * 80 + ks * 32 + lsel * 16;
                ldm_x4(pah[ks], sb + OPTH + ad);
                ldm_x4(pal[ks], sb + OPTL + ad);
            }
            int sx = (l >> 3) * 8 + (l & 7);   /* 0..31 */
#pragma unroll
            for (int nt = 0; nt < 8; nt++) {
                int gn = 8 * w + nt;
                unsigned ga = sb + OXH + c2 + sx * 1024 + ((unsigned)(gn ^ (sx & 7)) << 4);
                unsigned bh[4], bl[4];
                ldm_x4t(bh, ga);
                ldm_x4t(bl, ga + 65536u);
                mma(acc[nt], pah[0], bh);
                mma(acc[nt], pah[0], bl);
                mma(acc[nt], pal[0], bh);
                mma(acc[nt], pah[1], bh + 2);
                mma(acc[nt], pah[1], bl + 2);
                mma(acc[nt], pal[1], bh + 2);
            }
        }
        __syncthreads();  /* redp(tl) done; phase2 done reading buf/P^T */

        if (tl < NT) {
            /* reduce over warps, exp, P^T(tl) */
            int s0 = t >> 4, m0 = t & 15;
            float a0 = 0.f, a1 = 0.f;
#pragma unroll
            for (int ww = 0; ww < 8; ww++) {
                a0 += redp[ww * 544 + s0 * 17 + m0];
                a1 += redp[ww * 544 + (s0 + 16) * 17 + m0];
            }
            float e0 = __expf(a0), e1 = __expf(a1);  /* scores bounded: no max-sub */
            lsum += e0 + e1;
            __nv_bfloat16 h0 = __float2bfloat16(e0), h1 = __float2bfloat16(e1);
            __nv_bfloat16 o0 = __float2bfloat16(e0 - __bfloat162float(h0));
            __nv_bfloat16 o1 = __float2bfloat16(e1 - __bfloat162float(h1));
            *(__nv_bfloat16*)(smc + OPTH + m0 * 80 + s0 * 2) = h0;
            *(__nv_bfloat16*)(smc + OPTH + m0 * 80 + (s0 + 16) * 2) = h1;
            *(__nv_bfloat16*)(smc + OPTL + m0 * 80 + s0 * 2) = o0;
            *(__nv_bfloat16*)(smc + OPTL + m0 * 80 + (s0 + 16) * 2) = o1;

            /* convert(tl+1) into buf freed by phase2(tl-1) */
            if (tl + 1 < NT) {
#pragma unroll
                for (int i = 0; i < 16; i++) {
                    int idx = t + i * NTHREADS, r = idx >> 7, c4 = idx & 127;
                    uint2 h, lo;
                    splitf4(g[i], h, lo);
                    unsigned off = c2 + r * 1024 +
                                   ((((unsigned)c4 >> 1) ^ (r & 7)) << 4) + (c4 & 1) * 8;
                    *(uint2*)(smc + OXH + off) = h;
                    *(uint2*)(smc + OXL + off) = lo;
                }
            }
            /* stage tile tl+2 */
            if (tl + 2 < NT) {
#pragma unroll
                for (int i = 0; i < 16; i++)
                    g[i] = xb4[(size_t)(tl + 2) * TS * 128 + t + i * NTHREADS];
            }
        }
    }

    /* ---- per-chunk partials ---- */
    {
        size_t base = ((size_t)(b * CHUNKS + chunk) * MM) * DD;
#pragma unroll
        for (int nt = 0; nt < 8; nt++) {
            int d0 = w * 64 + nt * 8 + qc;
            *(float2*)&g_partA[base + (size_t)qr * DD + d0] =
                make_float2(acc[nt][0], acc[nt][1]);
            *(float2*)&g_partA[base + (size_t)(qr + 8) * DD + d0] =
                make_float2(acc[nt][2], acc[nt][3]);
        }
        lred[t] = lsum;
    }
    __syncthreads();
    if (t < MM) {
        float tot = 0.f;
#pragma unroll
        for (int i = 0; i < NTHREADS; i += MM) tot += lred[i + t];
        g_partL[(b * CHUNKS + chunk) * MM + t] = tot;
    }

    /* ---- last-CTA-per-batch fused merge ---- */
    __threadfence();
    __syncthreads();
    if (t == 0) {
        unsigned old = atomicAdd(&g_cnt[b], 1u);
        flag[0] = ((old & (CHUNKS - 1)) == (CHUNKS - 1)) ? 1u : 0u;
    }
    __syncthreads();
    if (flag[0]) {
        __threadfence();
        if (t < MM) {
            float sl = 0.f;
#pragma unroll
            for (int c2i = 0; c2i < CHUNKS; c2i++)
                sl += g_partL[(b * CHUNKS + c2i) * MM + t];
            linv[t] = 1.f / sl;
        }
        __syncthreads();
        float4* ob = (float4*)(out + (size_t)b * MM * DD);
#pragma unroll
        for (int i = 0; i < 8; i++) {
            int o = t + i * NTHREADS;
            int m = o >> 7, d4 = o & 127;
            float4 a = make_float4(0.f, 0.f, 0.f, 0.f);
#pragma unroll 8
            for (int c2i = 0; c2i < CHUNKS; c2i++) {
                const float4* pa =
                    (const float4*)&g_partA[(((size_t)(b * CHUNKS + c2i)) * MM + m) * DD];
                float4 v = pa[d4];
                a.x += v.x; a.y += v.y; a.z += v.z; a.w += v.w;
            }
            float inv = linv[m];
            ob[o] = make_float4(a.x * inv, a.y * inv, a.z * inv, a.w * inv);
        }
    }
}

extern "C" void kernel_launch(void* const* d_in, const int* in_sizes, int n_in,
                              void* d_out, int out_size) {
    const float* x = (const float*)d_in[0];
    const float* seeds = (const float*)d_in[1];
    float* out = (float*)d_out;

    cudaFuncSetAttribute(attn_pool_mma,
                         cudaFuncAttributeMaxDynamicSharedMemorySize, (int)SMEMSZ);
    dim3 grid(CHUNKS, BB);
    attn_pool_mma<<<grid, NTHREADS, SMEMSZ>>>(x, seeds, out);
}